// round 9
// baseline (speedup 1.0000x reference)
#include <cuda_runtime.h>
#include <cuda_bf16.h>

#define IMG_S   4096
#define N_DOTS  100
#define TW      64
#define TH      32
#define NTHREADS 256

// Barrier-free: warp w of each block owns a 64x4 strip (rows ty0+4w..+3).
// Lane l: row = ry0 + (l>>3), x = tx0 + (l&7)*4, two quads (+0, +32).
// Each lane culls dots l, l+32, l+64, l+96 against the strip; masks live in
// registers via intra-warp ballots. No shared memory, no __syncthreads.
__global__ __launch_bounds__(NTHREADS)
void PatchTrainer_dots_kernel(const float* __restrict__ patch,
                              const float* __restrict__ centers,
                              const float* __restrict__ radii,
                              const float* __restrict__ colors,
                              float* __restrict__ out) {
    const int tid  = threadIdx.x;
    const int lane = tid & 31;
    const int wid  = tid >> 5;
    const int tx0  = blockIdx.x * TW;
    const int ry0  = blockIdx.y * TH + (wid << 2);   // strip top row

    const float fx0 = (float)tx0, fx1 = (float)(tx0 + TW - 1);
    const float fy0 = (float)ry0, fy1 = (float)(ry0 + 3);

    // ---- per-lane transform + cull of 4 dots against the 64x4 strip ----
    float xc[4], yc[4], r2[4];
    unsigned im[4], cm[4];
    #pragma unroll
    for (int s = 0; s < 4; ++s) {
        const int d = lane + (s << 5);
        bool iv = false, cv = false;
        float xcs = 0.f, ycs = 0.f, rr = -1.f;
        if (d < N_DOTS) {
            const float2 c2 = __ldg(reinterpret_cast<const float2*>(centers) + d);
            xcs = floorf(__fmul_rn(c2.x, 4096.0f));
            ycs = floorf(__fmul_rn(c2.y, 4096.0f));
            const float r = floorf(__fmul_rn(__ldg(radii + d), 819.2f));
            rr = __fmul_rn(r, r);

            // Intersect: nearest strip pixel, reference rounding chain
            // (monotone rounding => never misses a covered pixel).
            const float nx = fminf(fmaxf(xcs, fx0), fx1);
            const float ny = fminf(fmaxf(ycs, fy0), fy1);
            const float ndx = __fadd_rn(nx, -xcs), ndy = __fadd_rn(ny, -ycs);
            iv = __fadd_rn(__fmul_rn(ndx, ndx), __fmul_rn(ndy, ndy)) <= rr;

            // Contains: farthest corner |dx|,|dy|, same rounding chain.
            const float ax = fmaxf(fabsf(__fadd_rn(fx0, -xcs)),
                                   fabsf(__fadd_rn(fx1, -xcs)));
            const float ay = fmaxf(fabsf(__fadd_rn(fy0, -ycs)),
                                   fabsf(__fadd_rn(fy1, -ycs)));
            cv = __fadd_rn(__fmul_rn(ax, ax), __fmul_rn(ay, ay)) <= rr;
        }
        xc[s] = xcs; yc[s] = ycs; r2[s] = rr;
        im[s] = __ballot_sync(0xffffffffu, iv);
        cm[s] = __ballot_sync(0xffffffffu, cv);
    }

    // ---- base = highest dot fully containing the strip; truncate masks ----
    int base = -1;
    if      (cm[3]) base = 96 + 31 - __clz(cm[3]);
    else if (cm[2]) base = 64 + 31 - __clz(cm[2]);
    else if (cm[1]) base = 32 + 31 - __clz(cm[1]);
    else if (cm[0]) base =      31 - __clz(cm[0]);

    if (base >= 0) {
        const int bw = base >> 5;
        const unsigned keep = 0xffffffffu << (base & 31);
        if      (bw == 0) { im[0] &= keep; }
        else if (bw == 1) { im[0] = 0; im[1] &= keep; }
        else if (bw == 2) { im[0] = 0; im[1] = 0; im[2] &= keep; }
        else              { im[0] = 0; im[1] = 0; im[2] = 0; im[3] &= keep; }
    }
    const int cnt = __popc(im[0]) + __popc(im[1]) + __popc(im[2]) + __popc(im[3]);

    const int x = tx0 + ((lane & 7) << 2);
    const int y = ry0 + (lane >> 3);
    const size_t pix   = (size_t)y * IMG_S + (size_t)x;
    const size_t plane = (size_t)IMG_S * IMG_S;

    // ---- fast path: solid strip ----
    if (base >= 0 && cnt == 1) {
        #pragma unroll
        for (int c = 0; c < 3; ++c) {
            const float col = __ldg(colors + base * 3 + c);
            const float4 o = make_float4(col, col, col, col);
            __stcs(reinterpret_cast<float4*>(out + c * plane + pix),      o);
            __stcs(reinterpret_cast<float4*>(out + c * plane + pix + 32), o);
        }
        return;
    }

    // ---- fast path: untouched strip (pure copy) ----
    if (cnt == 0) {
        #pragma unroll
        for (int c = 0; c < 3; ++c) {
            float4 a = *reinterpret_cast<const float4*>(patch + c * plane + pix);
            float4 b = *reinterpret_cast<const float4*>(patch + c * plane + pix + 32);
            __stcs(reinterpret_cast<float4*>(out + c * plane + pix),      a);
            __stcs(reinterpret_cast<float4*>(out + c * plane + pix + 32), b);
        }
        return;
    }

    // ---- per-pixel descending loop; params via shuffle from owner lane ----
    const float yf  = (float)y;
    const float x0f = (float)x;

    int b0 = -1, b1 = -1, b2 = -1, b3 = -1, b4 = -1, b5 = -1, b6 = -1, b7 = -1;
    bool done = false;

    #pragma unroll
    for (int w = 3; w >= 0; --w) {
        unsigned m = im[w];                 // warp-uniform
        while (m && !done) {
            const int bbit = 31 - __clz(m);
            m &= ~(1u << bbit);
            const int d = (w << 5) + bbit;

            const float xcs = __shfl_sync(0xffffffffu, xc[w], bbit);
            const float ycs = __shfl_sync(0xffffffffu, yc[w], bbit);
            const float rrs = __shfl_sync(0xffffffffu, r2[w], bbit);

            const float dy  = __fadd_rn(yf, -ycs);
            const float dy2 = __fmul_rn(dy, dy);
            const float dx0 = __fadd_rn(x0f, -xcs);
            // exact integer offsets in f32
            const float dx1 = dx0 + 1.0f,  dx2 = dx0 + 2.0f,  dx3 = dx0 + 3.0f;
            const float dx4 = dx0 + 32.0f, dx5 = dx0 + 33.0f, dx6 = dx0 + 34.0f,
                        dx7 = dx0 + 35.0f;

            if (b0 < 0 && __fadd_rn(__fmul_rn(dx0, dx0), dy2) <= rrs) b0 = d;
            if (b1 < 0 && __fadd_rn(__fmul_rn(dx1, dx1), dy2) <= rrs) b1 = d;
            if (b2 < 0 && __fadd_rn(__fmul_rn(dx2, dx2), dy2) <= rrs) b2 = d;
            if (b3 < 0 && __fadd_rn(__fmul_rn(dx3, dx3), dy2) <= rrs) b3 = d;
            if (b4 < 0 && __fadd_rn(__fmul_rn(dx4, dx4), dy2) <= rrs) b4 = d;
            if (b5 < 0 && __fadd_rn(__fmul_rn(dx5, dx5), dy2) <= rrs) b5 = d;
            if (b6 < 0 && __fadd_rn(__fmul_rn(dx6, dx6), dy2) <= rrs) b6 = d;
            if (b7 < 0 && __fadd_rn(__fmul_rn(dx7, dx7), dy2) <= rrs) b7 = d;

            const int mn = min(min(min(b0, b1), min(b2, b3)),
                               min(min(b4, b5), min(b6, b7)));
            done = __all_sync(0xffffffffu, mn >= 0);
        }
        if (done) break;
    }

    // ---- uniform-row shortcut: all 8 px share one dot -> 3 LDG + 6 STG ----
    const bool uni = (b0 >= 0) & (b0 == b1) & (b0 == b2) & (b0 == b3) &
                     (b0 == b4) & (b0 == b5) & (b0 == b6) & (b0 == b7);
    if (uni) {
        #pragma unroll
        for (int c = 0; c < 3; ++c) {
            const float col = __ldg(colors + b0 * 3 + c);
            const float4 o = make_float4(col, col, col, col);
            __stcs(reinterpret_cast<float4*>(out + c * plane + pix),      o);
            __stcs(reinterpret_cast<float4*>(out + c * plane + pix + 32), o);
        }
        return;
    }

    // ---- general emit ----
    const bool lo_in = (b0 < 0) | (b1 < 0) | (b2 < 0) | (b3 < 0);
    const bool hi_in = (b4 < 0) | (b5 < 0) | (b6 < 0) | (b7 < 0);

    const int i0 = max(b0, 0) * 3, i1 = max(b1, 0) * 3;
    const int i2 = max(b2, 0) * 3, i3 = max(b3, 0) * 3;
    const int i4 = max(b4, 0) * 3, i5 = max(b5, 0) * 3;
    const int i6 = max(b6, 0) * 3, i7 = max(b7, 0) * 3;

    #pragma unroll
    for (int c = 0; c < 3; ++c) {
        float4 vlo = make_float4(0.f, 0.f, 0.f, 0.f);
        float4 vhi = make_float4(0.f, 0.f, 0.f, 0.f);
        if (lo_in) vlo = *reinterpret_cast<const float4*>(patch + c * plane + pix);
        if (hi_in) vhi = *reinterpret_cast<const float4*>(patch + c * plane + pix + 32);

        float4 o, p;
        o.x = (b0 >= 0) ? __ldg(colors + i0 + c) : vlo.x;
        o.y = (b1 >= 0) ? __ldg(colors + i1 + c) : vlo.y;
        o.z = (b2 >= 0) ? __ldg(colors + i2 + c) : vlo.z;
        o.w = (b3 >= 0) ? __ldg(colors + i3 + c) : vlo.w;
        p.x = (b4 >= 0) ? __ldg(colors + i4 + c) : vhi.x;
        p.y = (b5 >= 0) ? __ldg(colors + i5 + c) : vhi.y;
        p.z = (b6 >= 0) ? __ldg(colors + i6 + c) : vhi.z;
        p.w = (b7 >= 0) ? __ldg(colors + i7 + c) : vhi.w;

        __stcs(reinterpret_cast<float4*>(out + c * plane + pix),      o);
        __stcs(reinterpret_cast<float4*>(out + c * plane + pix + 32), p);
    }
}

extern "C" void kernel_launch(void* const* d_in, const int* in_sizes, int n_in,
                              void* d_out, int out_size) {
    const float* adv_patch = (const float*)d_in[0];
    const float* centers   = (const float*)d_in[1];
    const float* radii     = (const float*)d_in[2];
    const float* colors    = (const float*)d_in[3];
    float* out = (float*)d_out;

    dim3 grid(IMG_S / TW, IMG_S / TH);  // 64 x 128 = 8192 blocks
    PatchTrainer_dots_kernel<<<grid, NTHREADS>>>(adv_patch, centers, radii,
                                                 colors, out);
}